// round 10
// baseline (speedup 1.0000x reference)
#include <cuda_runtime.h>

// ConsensusAttention: levels [B=8, N=1024, L=6, D=128] fp32.
// Local attention: each token attends to <=13 neighbors (dy^2+dx^2 <= 4 on 32x32 grid),
// self sim fixed at -0.0005, others = (q_i . k_j)/sqrt(D) with k = normalized levels.
// Kernel 1: per-row scale = rsqrt(|v|^2) * log2(e)/sqrt(D)  (8 lanes/row).
// Kernel 2: local attention, 16 lanes/token (2 tokens/warp), packed FFMA2,
// TRIPLE-buffered neighbor pipeline (loads issue ~2 stages / ~300cyc before use,
// covering L2 hit latency), all 12 per-neighbor scales preloaded upfront.

#define B_DIM 8
#define N_TOK 1024
#define L_DIM 6
#define D_DIM 128
#define ROWS (B_DIM * N_TOK * L_DIM)   // 49152
#define ROW_STRIDE (L_DIM * D_DIM)     // 768 floats between consecutive j
#define ROW_U2 (ROW_STRIDE / 4)        // 192 ulonglong2 per row

// sim->exp2 scale: (1/sqrt(128)) * log2(e)
#define C_SC 0.12751742119567576f

__device__ float g_scale[ROWS];   // rsqrt(|row|^2) * C_SC   (always > 0)

// ---- packed f32x2 helpers (Blackwell FFMA2 path, PTX-only) ----
__device__ __forceinline__ unsigned long long pk2(float lo, float hi) {
    unsigned long long r;
    asm("mov.b64 %0, {%1, %2};" : "=l"(r) : "f"(lo), "f"(hi));
    return r;
}
__device__ __forceinline__ unsigned long long pk_fma(unsigned long long a,
                                                     unsigned long long b,
                                                     unsigned long long c) {
    unsigned long long d;
    asm("fma.rn.f32x2 %0, %1, %2, %3;" : "=l"(d) : "l"(a), "l"(b), "l"(c));
    return d;
}
__device__ __forceinline__ unsigned long long pk_mul(unsigned long long a,
                                                     unsigned long long b) {
    unsigned long long d;
    asm("mul.rn.f32x2 %0, %1, %2;" : "=l"(d) : "l"(a), "l"(b));
    return d;
}
__device__ __forceinline__ float pk_hadd(unsigned long long a) {
    float lo, hi;
    asm("mov.b64 {%0, %1}, %2;" : "=f"(lo), "=f"(hi) : "l"(a));
    return lo + hi;
}
__device__ __forceinline__ float rsqrt_approx(float x) {
    float r;
    asm("rsqrt.approx.f32 %0, %1;" : "=f"(r) : "f"(x));
    return r;
}
__device__ __forceinline__ float ex2_approx(float x) {
    float r;
    asm("ex2.approx.f32 %0, %1;" : "=f"(r) : "f"(x));
    return r;
}

// Kernel 1: per-row softmax scale. 8 lanes per row, 4 rows per warp.
__global__ __launch_bounds__(256) void norm_kernel(const float* __restrict__ in) {
    int row  = (blockIdx.x * 256 + threadIdx.x) >> 3;
    int lane = threadIdx.x & 7;
    const float4* p = (const float4*)(in + (size_t)row * D_DIM);
    float4 v0 = p[lane], v1 = p[8 + lane], v2 = p[16 + lane], v3 = p[24 + lane];
    float s = v0.x * v0.x + v0.y * v0.y + v0.z * v0.z + v0.w * v0.w
            + v1.x * v1.x + v1.y * v1.y + v1.z * v1.z + v1.w * v1.w
            + v2.x * v2.x + v2.y * v2.y + v2.z * v2.z + v2.w * v2.w
            + v3.x * v3.x + v3.y * v3.y + v3.z * v3.z + v3.w * v3.w;
    s += __shfl_xor_sync(0xffffffffu, s, 1);
    s += __shfl_xor_sync(0xffffffffu, s, 2);
    s += __shfl_xor_sync(0xffffffffu, s, 4);
    if (lane == 0) g_scale[row] = rsqrt_approx(fmaxf(s, 1e-24f)) * C_SC;
}

// Kernel 2: local attention. 16 lanes/token (2 tokens/warp); lane owns 8 of
// 128 d-elements as 2 ulonglong2 (= 4 packed f32x2).
__global__ __launch_bounds__(256, 3) void attn_kernel(const float* __restrict__ in,
                                                      float* __restrict__ out) {
    const int tid  = threadIdx.x;
    const int gid  = (blockIdx.x * 256 + tid) >> 4;  // token id, 0..49151
    const int lane = tid & 15;

    const int i  = gid & (N_TOK - 1);
    const int bl = gid >> 10;          // b * L + l
    const int b  = bl / L_DIM;
    const int l  = bl - b * L_DIM;
    const int y  = i >> 5;
    const int x  = i & 31;

    // self row pointer; neighbor j = i + doff is at qr + doff*ROW_U2
    const ulonglong2* qr =
        (const ulonglong2*)(in + ((size_t)b * N_TOK * L_DIM + l) * D_DIM
                               + (size_t)i * ROW_STRIDE);
    const float* scp = g_scale + ((size_t)(b * N_TOK + i) * L_DIM + l);  // + doff*L_DIM

    // 12 non-self neighbors with dy^2 + dx^2 <= 4
    const int dys[12] = {-2, -1, -1, -1,  0,  0, 0, 0, 1, 1, 1, 2};
    const int dxs[12] = { 0, -1,  0,  1, -2, -1, 1, 2,-1, 0, 1, 0};

    // All 12 neighbor scales upfront (sc > 0 iff in-bounds; OOB -> 0 -> w = 0)
    float sc[12];
    int   ok[12];
    #pragma unroll
    for (int t = 0; t < 12; t++) {
        ok[t] = (((unsigned)(y + dys[t]) < 32u) & ((unsigned)(x + dxs[t]) < 32u)) ? 1 : 0;
        const int doff = dys[t] * 32 + dxs[t];
        sc[t] = ok[t] ? scp[doff * L_DIM] : 0.0f;
    }

    const ulonglong2 q0 = qr[lane], q1 = qr[16 + lane];

    // Self term: sim = -0.0005 exactly; value = q.
    const float wself = 0.9995001249791693f;   // exp(-0.0005)
    float ssum = wself;
    const unsigned long long ws2 = pk2(wself, wself);
    unsigned long long a00 = pk_mul(ws2, q0.x);
    unsigned long long a01 = pk_mul(ws2, q0.y);
    unsigned long long a10 = pk_mul(ws2, q1.x);
    unsigned long long a11 = pk_mul(ws2, q1.y);

    ulonglong2 vb[3][2];   // triple buffer: [slot][d-chunk]

    // Prologue: load neighbors 0 and 1 (slots 0, 1)
    #pragma unroll
    for (int t = 0; t < 2; t++) {
        const int doff = dys[t] * 32 + dxs[t];
        const int po = ok[t] ? doff * ROW_U2 : 0;
        vb[t][0] = qr[po + lane];
        vb[t][1] = qr[po + 16 + lane];
    }

    #pragma unroll
    for (int t = 0; t < 12; t++) {
        const int cur = t % 3;

        // Prefetch neighbor t+2 (two stages / ~300 cyc ahead of its use)
        if (t < 10) {
            const int nx = (t + 2) % 3;
            const int doff = dys[t + 2] * 32 + dxs[t + 2];   // compile-time constant
            const int po = ok[t + 2] ? doff * ROW_U2 : 0;
            vb[nx][0] = qr[po + lane];
            vb[nx][1] = qr[po + 16 + lane];
        }

        // Packed partial dot product q.v (4 FFMA2), then horizontal add
        unsigned long long d2 = pk_mul(q0.x, vb[cur][0].x);
        d2 = pk_fma(q0.y, vb[cur][0].y, d2);
        d2 = pk_fma(q1.x, vb[cur][1].x, d2);
        d2 = pk_fma(q1.y, vb[cur][1].y, d2);
        float dp = pk_hadd(d2);

        // 16-lane butterfly reduce (each SHFL serves both tokens in the warp)
        dp += __shfl_xor_sync(0xffffffffu, dp, 1);
        dp += __shfl_xor_sync(0xffffffffu, dp, 2);
        dp += __shfl_xor_sync(0xffffffffu, dp, 4);
        dp += __shfl_xor_sync(0xffffffffu, dp, 8);

        // w = sc>0 ? 2^(dp*sc) : 0   (OOB neighbors contribute nothing)
        float w = (sc[t] > 0.0f) ? ex2_approx(dp * sc[t]) : 0.0f;
        ssum += w;
        const unsigned long long w2 = pk2(w, w);
        a00 = pk_fma(w2, vb[cur][0].x, a00);
        a01 = pk_fma(w2, vb[cur][0].y, a01);
        a10 = pk_fma(w2, vb[cur][1].x, a10);
        a11 = pk_fma(w2, vb[cur][1].y, a11);
    }

    const float inv = 1.0f / ssum;
    const unsigned long long inv2 = pk2(inv, inv);
    ulonglong2 o0, o1;
    o0.x = pk_mul(a00, inv2);
    o0.y = pk_mul(a01, inv2);
    o1.x = pk_mul(a10, inv2);
    o1.y = pk_mul(a11, inv2);

    ulonglong2* orow = (ulonglong2*)(out + ((size_t)(b * N_TOK + i) * L_DIM + l) * D_DIM);
    orow[lane] = o0;
    orow[16 + lane] = o1;
}

extern "C" void kernel_launch(void* const* d_in, const int* in_sizes, int n_in,
                              void* d_out, int out_size) {
    const float* in = (const float*)d_in[0];
    float* out = (float*)d_out;
    norm_kernel<<<ROWS / 32, 256>>>(in);         // 1536 blocks, 4 rows per warp
    attn_kernel<<<ROWS / 16, 256>>>(in, out);    // 3072 blocks, 16 tokens each
}

// round 11
// speedup vs baseline: 1.1381x; 1.1381x over previous
#include <cuda_runtime.h>

// ConsensusAttention: levels [B=8, N=1024, L=6, D=128] fp32.
// Local attention: each token attends to <=13 neighbors (dy^2+dx^2 <= 4 on 32x32 grid),
// self sim fixed at -0.0005, others = (q_i . k_j)/sqrt(D) with k = normalized levels.
//
// Kernel 1: per-row scale = rsqrt(|v|^2) * log2(e)/sqrt(D).
// Kernel 2: local attention over ADJACENT TOKEN PAIRS (i, i+1): the pair's
// neighbor union is 18 rows (9/token vs 13/token) -> ~31% less L1 traffic.
// 16 lanes per pair; packed FFMA2; double-buffered row pipeline; one EX2/weight.
// Kernel 2 launches with Programmatic Dependent Launch and grid-syncs after its
// scale-independent prologue, overlapping kernel 1's execution.

#define B_DIM 8
#define N_TOK 1024
#define L_DIM 6
#define D_DIM 128
#define ROWS (B_DIM * N_TOK * L_DIM)   // 49152
#define ROW_STRIDE (L_DIM * D_DIM)     // 768 floats between consecutive j
#define ROW_U2 (ROW_STRIDE / 4)        // 192 ulonglong2 per row
#define N_PAIRS (ROWS / 2)             // 24576

// sim->exp2 scale: (1/sqrt(128)) * log2(e)
#define C_SC 0.12751742119567576f

__device__ float g_scale[ROWS];   // rsqrt(|row|^2) * C_SC   (always > 0)

// ---- packed f32x2 helpers (Blackwell FFMA2 path, PTX-only) ----
__device__ __forceinline__ unsigned long long pk2(float lo, float hi) {
    unsigned long long r;
    asm("mov.b64 %0, {%1, %2};" : "=l"(r) : "f"(lo), "f"(hi));
    return r;
}
__device__ __forceinline__ unsigned long long pk_fma(unsigned long long a,
                                                     unsigned long long b,
                                                     unsigned long long c) {
    unsigned long long d;
    asm("fma.rn.f32x2 %0, %1, %2, %3;" : "=l"(d) : "l"(a), "l"(b), "l"(c));
    return d;
}
__device__ __forceinline__ unsigned long long pk_mul(unsigned long long a,
                                                     unsigned long long b) {
    unsigned long long d;
    asm("mul.rn.f32x2 %0, %1, %2;" : "=l"(d) : "l"(a), "l"(b));
    return d;
}
__device__ __forceinline__ float pk_hadd(unsigned long long a) {
    float lo, hi;
    asm("mov.b64 {%0, %1}, %2;" : "=f"(lo), "=f"(hi) : "l"(a));
    return lo + hi;
}
__device__ __forceinline__ float rsqrt_approx(float x) {
    float r;
    asm("rsqrt.approx.f32 %0, %1;" : "=f"(r) : "f"(x));
    return r;
}
__device__ __forceinline__ float ex2_approx(float x) {
    float r;
    asm("ex2.approx.f32 %0, %1;" : "=f"(r) : "f"(x));
    return r;
}

// Kernel 1: per-row softmax scale. 8 lanes per row, 4 rows per warp.
__global__ __launch_bounds__(256) void norm_kernel(const float* __restrict__ in) {
    int row  = (blockIdx.x * 256 + threadIdx.x) >> 3;
    int lane = threadIdx.x & 7;
    const float4* p = (const float4*)(in + (size_t)row * D_DIM);
    float4 v0 = p[lane], v1 = p[8 + lane], v2 = p[16 + lane], v3 = p[24 + lane];
    float s = v0.x * v0.x + v0.y * v0.y + v0.z * v0.z + v0.w * v0.w
            + v1.x * v1.x + v1.y * v1.y + v1.z * v1.z + v1.w * v1.w
            + v2.x * v2.x + v2.y * v2.y + v2.z * v2.z + v2.w * v2.w
            + v3.x * v3.x + v3.y * v3.y + v3.z * v3.z + v3.w * v3.w;
    s += __shfl_xor_sync(0xffffffffu, s, 1);
    s += __shfl_xor_sync(0xffffffffu, s, 2);
    s += __shfl_xor_sync(0xffffffffu, s, 4);
    if (lane == 0) g_scale[row] = rsqrt_approx(fmaxf(s, 1e-24f)) * C_SC;
    cudaTriggerProgrammaticLaunchCompletion();
}

// Kernel 2: pair attention. 16 lanes per pair; lane owns 8 d-elements of each
// row as 2 ulonglong2 (4 packed f32x2). 18-row union, roles compile-time.
__global__ __launch_bounds__(256, 3) void attn_kernel(const float* __restrict__ in,
                                                      float* __restrict__ out) {
    const int tid  = threadIdx.x;
    const int pid  = (blockIdx.x * 256 + tid) >> 4;  // pair id, 0..24575
    const int lane = tid & 15;

    const int ps = pid & 511;          // pair within (b,l) slice
    const int bl = pid >> 9;           // b * L + l
    const int b  = bl / L_DIM;
    const int l  = bl - b * L_DIM;
    const int y  = ps >> 4;
    const int x  = (ps & 15) << 1;     // even column; pair = (x, x+1)
    const int i  = (y << 5) | x;

    const ulonglong2* qr =
        (const ulonglong2*)(in + ((size_t)b * N_TOK * L_DIM + l) * D_DIM
                               + (size_t)i * ROW_STRIDE);
    const float* scp = g_scale + ((size_t)(b * N_TOK + i) * L_DIM + l);  // + doff*L_DIM

    // q rows for both tokens (A at i, B at i+1)
    const ulonglong2 qA0 = qr[lane],          qA1 = qr[16 + lane];
    const ulonglong2 qB0 = qr[ROW_U2 + lane], qB1 = qr[ROW_U2 + 16 + lane];

    // Self terms: sim = -0.0005 exactly; value = own row.
    const float wself = 0.9995001249791693f;   // exp(-0.0005)
    float ssumA = wself, ssumB = wself;
    const unsigned long long ws2 = pk2(wself, wself);
    unsigned long long aA0 = pk_mul(ws2, qA0.x), aA1 = pk_mul(ws2, qA0.y);
    unsigned long long aA2 = pk_mul(ws2, qA1.x), aA3 = pk_mul(ws2, qA1.y);
    unsigned long long aB0 = pk_mul(ws2, qB0.x), aB1 = pk_mul(ws2, qB0.y);
    unsigned long long aB2 = pk_mul(ws2, qB1.x), aB3 = pk_mul(ws2, qB1.y);

    // 18-row union for the pair; roles are compile-time constants.
    // rA: row is a (non-self) neighbor of A; rB: of B.
    const int dys[18] = {-2,-2,-1,-1,-1,-1, 0, 0, 0, 0, 0, 0, 1, 1, 1, 1, 2, 2};
    const int dxs[18] = { 0, 1,-1, 0, 1, 2,-2,-1, 0, 1, 2, 3,-1, 0, 1, 2, 0, 1};
    const int rA [18] = { 1, 0, 1, 1, 1, 0, 1, 1, 0, 1, 1, 0, 1, 1, 1, 0, 1, 0};
    const int rB [18] = { 0, 1, 0, 1, 1, 1, 0, 1, 1, 0, 1, 1, 0, 1, 1, 1, 0, 1};

    ulonglong2 vb[2][2];   // double buffer: [parity][d-chunk]
    float      sc[2];      // row scale; 0 if the row is off-grid -> w = 0

    // Prologue: row 0 data load (scale-independent)
    {
        const int doff = dys[0] * 32 + dxs[0];
        bool ok = ((unsigned)(y + dys[0]) < 32u) & ((unsigned)(x + dxs[0]) < 32u);
        const int po = ok ? doff * ROW_U2 : 0;
        vb[0][0] = qr[po + lane];
        vb[0][1] = qr[po + 16 + lane];
    }

    // Wait for norm_kernel results; everything above overlapped with it.
    cudaGridDependencySynchronize();

    {
        bool ok = ((unsigned)(y + dys[0]) < 32u) & ((unsigned)(x + dxs[0]) < 32u);
        sc[0] = ok ? scp[(dys[0] * 32 + dxs[0]) * L_DIM] : 0.0f;
    }

    #pragma unroll
    for (int t = 0; t < 18; t++) {
        const int cur = t & 1, nxt = cur ^ 1;

        // Prefetch next row + its scale
        if (t < 17) {
            const int doff = dys[t + 1] * 32 + dxs[t + 1];   // compile-time constant
            bool ok = ((unsigned)(y + dys[t + 1]) < 32u) & ((unsigned)(x + dxs[t + 1]) < 32u);
            const int po = ok ? doff * ROW_U2 : 0;
            sc[nxt] = ok ? scp[doff * L_DIM] : 0.0f;
            vb[nxt][0] = qr[po + lane];
            vb[nxt][1] = qr[po + 16 + lane];
        }

        const ulonglong2 v0 = vb[cur][0], v1 = vb[cur][1];

        // dp for each role this row serves (dead code eliminated per constant role)
        float dpA = 0.0f, dpB = 0.0f;
        if (rA[t]) {
            unsigned long long d2 = pk_mul(qA0.x, v0.x);
            d2 = pk_fma(qA0.y, v0.y, d2);
            d2 = pk_fma(qA1.x, v1.x, d2);
            d2 = pk_fma(qA1.y, v1.y, d2);
            dpA = pk_hadd(d2);
        }
        if (rB[t]) {
            unsigned long long d2 = pk_mul(qB0.x, v0.x);
            d2 = pk_fma(qB0.y, v0.y, d2);
            d2 = pk_fma(qB1.x, v1.x, d2);
            d2 = pk_fma(qB1.y, v1.y, d2);
            dpB = pk_hadd(d2);
        }

        // 16-lane butterfly reduce; chains interleave when both roles present
        #pragma unroll
        for (int m = 1; m < 16; m <<= 1) {
            if (rA[t]) dpA += __shfl_xor_sync(0xffffffffu, dpA, m);
            if (rB[t]) dpB += __shfl_xor_sync(0xffffffffu, dpB, m);
        }

        const float s = sc[cur];
        if (rA[t]) {
            float w = (s > 0.0f) ? ex2_approx(dpA * s) : 0.0f;
            ssumA += w;
            const unsigned long long w2 = pk2(w, w);
            aA0 = pk_fma(w2, v0.x, aA0);
            aA1 = pk_fma(w2, v0.y, aA1);
            aA2 = pk_fma(w2, v1.x, aA2);
            aA3 = pk_fma(w2, v1.y, aA3);
        }
        if (rB[t]) {
            float w = (s > 0.0f) ? ex2_approx(dpB * s) : 0.0f;
            ssumB += w;
            const unsigned long long w2 = pk2(w, w);
            aB0 = pk_fma(w2, v0.x, aB0);
            aB1 = pk_fma(w2, v0.y, aB1);
            aB2 = pk_fma(w2, v1.x, aB2);
            aB3 = pk_fma(w2, v1.y, aB3);
        }
    }

    ulonglong2* orow = (ulonglong2*)(out + ((size_t)(b * N_TOK + i) * L_DIM + l) * D_DIM);

    const float invA = 1.0f / ssumA;
    const unsigned long long iA = pk2(invA, invA);
    ulonglong2 oA0, oA1;
    oA0.x = pk_mul(aA0, iA); oA0.y = pk_mul(aA1, iA);
    oA1.x = pk_mul(aA2, iA); oA1.y = pk_mul(aA3, iA);
    orow[lane] = oA0;
    orow[16 + lane] = oA1;

    const float invB = 1.0f / ssumB;
    const unsigned long long iB = pk2(invB, invB);
    ulonglong2 oB0, oB1;
    oB0.x = pk_mul(aB0, iB); oB0.y = pk_mul(aB1, iB);
    oB1.x = pk_mul(aB2, iB); oB1.y = pk_mul(aB3, iB);
    orow[ROW_U2 + lane] = oB0;
    orow[ROW_U2 + 16 + lane] = oB1;
}

extern "C" void kernel_launch(void* const* d_in, const int* in_sizes, int n_in,
                              void* d_out, int out_size) {
    const float* in = (const float*)d_in[0];
    float* out = (float*)d_out;

    norm_kernel<<<ROWS / 32, 256>>>(in);   // 1536 blocks

    // attn with Programmatic Dependent Launch: overlaps its prologue with norm.
    cudaLaunchConfig_t cfg = {};
    cfg.gridDim  = dim3(N_PAIRS * 16 / 256, 1, 1);   // 1536 blocks
    cfg.blockDim = dim3(256, 1, 1);
    cudaLaunchAttribute attr[1];
    attr[0].id = cudaLaunchAttributeProgrammaticStreamSerialization;
    attr[0].val.programmaticStreamSerializationAllowed = 1;
    cfg.attrs = attr;
    cfg.numAttrs = 1;
    cudaLaunchKernelEx(&cfg, attn_kernel, in, out);
}

// round 12
// speedup vs baseline: 1.2455x; 1.0943x over previous
#include <cuda_runtime.h>
#include <cuda.h>
#include <cstdint>

// ConsensusAttention: levels [B=8, N=1024, L=6, D=128] fp32.
// Local attention: each token attends to <=13 neighbors (dy^2+dx^2 <= 4 on 32x32 grid),
// self sim fixed at -0.0005, others = (q_i . k_j)/sqrt(D) with k = normalized levels.
//
// Kernel 1: per-row scale = rsqrt(|v|^2) * log2(e)/sqrt(D)  (+ PDL trigger).
// Kernel 2: block = 8x8 token tile of one (b,l) slice. ONE 5D TMA stages the
// 12x12 halo (73.7KB) into smem with OOB zero-fill (edge handling for free).
// Inner loop is pure LDS + packed FFMA2 with compile-time offsets; per-token
// chunk rotation keeps every LDS.128 phase bank-conflict-free.

#define B_DIM 8
#define N_TOK 1024
#define L_DIM 6
#define D_DIM 128
#define ROWS (B_DIM * N_TOK * L_DIM)   // 49152
#define C_SC 0.12751742119567576f      // (1/sqrt(128)) * log2(e)

#define TILE_BYTES  (144 * 512)        // 12x12 rows x 512B
#define SMEM_TILE_OFF 1024             // tile starts 1024B into dynamic smem
#define SMEM_TOTAL (SMEM_TILE_OFF + TILE_BYTES)   // 74752

__device__ float g_scale[ROWS];   // rsqrt(|row|^2) * C_SC  (always > 0)

// ---- packed f32x2 helpers ----
__device__ __forceinline__ unsigned long long pk2(float lo, float hi) {
    unsigned long long r;
    asm("mov.b64 %0, {%1, %2};" : "=l"(r) : "f"(lo), "f"(hi));
    return r;
}
__device__ __forceinline__ unsigned long long pk_fma(unsigned long long a,
                                                     unsigned long long b,
                                                     unsigned long long c) {
    unsigned long long d;
    asm("fma.rn.f32x2 %0, %1, %2, %3;" : "=l"(d) : "l"(a), "l"(b), "l"(c));
    return d;
}
__device__ __forceinline__ unsigned long long pk_mul(unsigned long long a,
                                                     unsigned long long b) {
    unsigned long long d;
    asm("mul.rn.f32x2 %0, %1, %2;" : "=l"(d) : "l"(a), "l"(b));
    return d;
}
__device__ __forceinline__ unsigned long long pk_add(unsigned long long a,
                                                     unsigned long long b) {
    unsigned long long d;
    asm("add.rn.f32x2 %0, %1, %2;" : "=l"(d) : "l"(a), "l"(b));
    return d;
}
__device__ __forceinline__ float pk_hadd(unsigned long long a) {
    float lo, hi;
    asm("mov.b64 {%0, %1}, %2;" : "=f"(lo), "=f"(hi) : "l"(a));
    return lo + hi;
}
__device__ __forceinline__ float rsqrt_approx(float x) {
    float r; asm("rsqrt.approx.f32 %0, %1;" : "=f"(r) : "f"(x)); return r;
}
__device__ __forceinline__ float ex2_approx(float x) {
    float r; asm("ex2.approx.f32 %0, %1;" : "=f"(r) : "f"(x)); return r;
}
__device__ __forceinline__ uint32_t smem_u32(const void* p) {
    uint32_t a;
    asm("{ .reg .u64 t; cvta.to.shared.u64 t, %1; cvt.u32.u64 %0, t; }" : "=r"(a) : "l"(p));
    return a;
}
__device__ __forceinline__ ulonglong2 lds128(uint32_t addr) {
    ulonglong2 r;
    asm volatile("ld.shared.v2.u64 {%0, %1}, [%2];" : "=l"(r.x), "=l"(r.y) : "r"(addr));
    return r;
}

// Kernel 1: per-row softmax scale. 8 lanes per row, 4 rows per warp.
__global__ __launch_bounds__(256) void norm_kernel(const float* __restrict__ in) {
    int row  = (blockIdx.x * 256 + threadIdx.x) >> 3;
    int lane = threadIdx.x & 7;
    const float4* p = (const float4*)(in + (size_t)row * D_DIM);
    float4 v0 = p[lane], v1 = p[8 + lane], v2 = p[16 + lane], v3 = p[24 + lane];
    float s = v0.x * v0.x + v0.y * v0.y + v0.z * v0.z + v0.w * v0.w
            + v1.x * v1.x + v1.y * v1.y + v1.z * v1.z + v1.w * v1.w
            + v2.x * v2.x + v2.y * v2.y + v2.z * v2.z + v2.w * v2.w
            + v3.x * v3.x + v3.y * v3.y + v3.z * v3.z + v3.w * v3.w;
    s += __shfl_xor_sync(0xffffffffu, s, 1);
    s += __shfl_xor_sync(0xffffffffu, s, 2);
    s += __shfl_xor_sync(0xffffffffu, s, 4);
    if (lane == 0) g_scale[row] = rsqrt_approx(fmaxf(s, 1e-24f)) * C_SC;
    cudaTriggerProgrammaticLaunchCompletion();
}

// Kernel 2: tile attention. 768 blocks x 256 threads; thread = one token,
// 4 lanes/token (8 tokens/warp). v/q from smem staged by one 5D TMA.
__global__ __launch_bounds__(256, 2) void attn_kernel(
    const __grid_constant__ CUtensorMap tmap,
    float* __restrict__ out)
{
    extern __shared__ char smem[];
    const uint32_t sbase = smem_u32(smem);
    const uint32_t MBAR  = sbase;                 // 8B mbarrier
    float* scales        = (float*)(smem + 16);   // 144 floats
    const uint32_t TILE  = sbase + SMEM_TILE_OFF; // 144 rows x 512B

    const int tid   = threadIdx.x;
    const int bid   = blockIdx.x;
    const int slice = bid >> 4;            // 0..47  (b*6 + l)
    const int tile  = bid & 15;
    const int b  = slice / L_DIM;
    const int l  = slice - b * L_DIM;
    const int ty = tile >> 2, tx = tile & 3;
    const int gy0 = ty * 8 - 2, gx0 = tx * 8 - 2;

    // mbarrier init, then one thread issues the 5D TMA (input-only: pre-PDL)
    if (tid == 0) {
        asm volatile("mbarrier.init.shared.b64 [%0], %1;" :: "r"(MBAR), "r"(1) : "memory");
    }
    __syncthreads();
    if (tid == 0) {
        asm volatile("mbarrier.arrive.expect_tx.shared.b64 _, [%0], %1;"
                     :: "r"(MBAR), "r"((uint32_t)TILE_BYTES) : "memory");
        asm volatile(
            "cp.async.bulk.tensor.5d.shared::cta.global.tile.mbarrier::complete_tx::bytes "
            "[%0], [%1, {%2, %3, %4, %5, %6}], [%7];"
            :: "r"(TILE), "l"(&tmap),
               "r"(0), "r"(gx0), "r"(gy0), "r"(l), "r"(b),
               "r"(MBAR) : "memory");
    }

    // Wait for norm_kernel's g_scale (TMA issue above overlapped with it)
    cudaGridDependencySynchronize();

    // Stage the 144 row scales (0 for off-grid rows)
    if (tid < 144) {
        int ly = tid / 12, lx = tid - ly * 12;
        int gy = gy0 + ly, gx = gx0 + lx;
        bool ok = ((unsigned)gy < 32u) & ((unsigned)gx < 32u);
        scales[tid] = ok ? g_scale[((b * N_TOK + (gy << 5) + gx) * L_DIM) + l] : 0.0f;
    }
    __syncthreads();

    // Wait for TMA completion
    {
        uint32_t done;
        asm volatile(
            "{\n\t.reg .pred p;\n\t"
            "mbarrier.try_wait.parity.shared.b64 p, [%1], %2;\n\t"
            "selp.b32 %0, 1, 0, p;\n\t}"
            : "=r"(done) : "r"(MBAR), "r"(0u) : "memory");
        if (!done) {
            asm volatile(
                "{\n\t.reg .pred P1;\n\t"
                "W_%=:\n\t"
                "mbarrier.try_wait.parity.shared.b64 P1, [%0], %1;\n\t"
                "@P1 bra.uni D_%=;\n\t"
                "bra.uni W_%=;\n\t"
                "D_%=:\n\t}"
                :: "r"(MBAR), "r"(0u) : "memory");
        }
    }

    // Thread -> token mapping
    const int t  = tid >> 2;         // token 0..63 within tile
    const int j  = tid & 3;          // lane within token
    const int ly = t >> 3, lx = t & 7;

    // Rotated chunk offsets: lane j owns chunks (4*lx + j + 4i) & 31, i=0..7.
    // Guarantees every LDS.128 phase (8 lanes = 2 tokens) covers 32 distinct banks.
    uint32_t coff[8];
    #pragma unroll
    for (int i = 0; i < 8; i++)
        coff[i] = (uint32_t)(((4 * lx + j + 4 * i) & 31) * 16);

    // q from self row
    const uint32_t self_ra = TILE + (uint32_t)(((ly + 2) * 12 + (lx + 2)) * 512);
    ulonglong2 q[8];
    #pragma unroll
    for (int i = 0; i < 8; i++) q[i] = lds128(self_ra + coff[i]);

    // Self term: sim = -0.0005 exactly
    const float wself = 0.9995001249791693f;   // exp(-0.0005)
    float ssum = wself;
    const unsigned long long ws2 = pk2(wself, wself);
    ulonglong2 acc[8];
    #pragma unroll
    for (int i = 0; i < 8; i++) {
        acc[i].x = pk_mul(ws2, q[i].x);
        acc[i].y = pk_mul(ws2, q[i].y);
    }

    // 12 non-self neighbors (dy^2+dx^2 <= 4); rows outside the grid are
    // zero-filled by TMA and have scale 0 -> w = 0, zero contribution.
    const int dys[12] = {-2, -1, -1, -1,  0,  0, 0, 0, 1, 1, 1, 2};
    const int dxs[12] = { 0, -1,  0,  1, -2, -1, 1, 2,-1, 0, 1, 0};

    #pragma unroll
    for (int n = 0; n < 12; n++) {
        const int srow = (ly + 2 + dys[n]) * 12 + (lx + 2 + dxs[n]);
        const uint32_t ra = TILE + (uint32_t)(srow * 512);

        ulonglong2 v[8];
        #pragma unroll
        for (int i = 0; i < 8; i++) v[i] = lds128(ra + coff[i]);

        // Two interleaved dp chains (ILP), then combine
        unsigned long long dA = pk_mul(q[0].x, v[0].x);
        dA = pk_fma(q[0].y, v[0].y, dA);
        unsigned long long dB = pk_mul(q[1].x, v[1].x);
        dB = pk_fma(q[1].y, v[1].y, dB);
        #pragma unroll
        for (int i = 2; i < 8; i += 2) {
            dA = pk_fma(q[i].x,     v[i].x,     dA);
            dA = pk_fma(q[i].y,     v[i].y,     dA);
            dB = pk_fma(q[i + 1].x, v[i + 1].x, dB);
            dB = pk_fma(q[i + 1].y, v[i + 1].y, dB);
        }
        float dp = pk_hadd(pk_add(dA, dB));

        // 4-lane butterfly (each SHFL serves all 8 tokens in the warp)
        dp += __shfl_xor_sync(0xffffffffu, dp, 1);
        dp += __shfl_xor_sync(0xffffffffu, dp, 2);

        const float sc = scales[srow];
        float w = (sc > 0.0f) ? ex2_approx(dp * sc) : 0.0f;
        ssum += w;
        const unsigned long long w2 = pk2(w, w);
        #pragma unroll
        for (int i = 0; i < 8; i++) {
            acc[i].x = pk_fma(w2, v[i].x, acc[i].x);
            acc[i].y = pk_fma(w2, v[i].y, acc[i].y);
        }
    }

    // Normalize and store (lane's chunks go back to their rotated positions)
    const int gtok = ((ty * 8 + ly) << 5) + (tx * 8 + lx);
    ulonglong2* orow =
        (ulonglong2*)(out + ((size_t)(b * N_TOK + gtok) * L_DIM + l) * D_DIM);
    const float inv = 1.0f / ssum;
    const unsigned long long inv2 = pk2(inv, inv);
    #pragma unroll
    for (int i = 0; i < 8; i++) {
        ulonglong2 o;
        o.x = pk_mul(acc[i].x, inv2);
        o.y = pk_mul(acc[i].y, inv2);
        orow[coff[i] >> 4] = o;
    }
}

extern "C" void kernel_launch(void* const* d_in, const int* in_sizes, int n_in,
                              void* d_out, int out_size) {
    const float* in = (const float*)d_in[0];
    float* out = (float*)d_out;

    // Build the 5D tensor map (host-side; no -lcuda needed via runtime entry point)
    typedef CUresult (*EncodeFn)(CUtensorMap*, CUtensorMapDataType, cuuint32_t, void*,
                                 const cuuint64_t*, const cuuint64_t*, const cuuint32_t*,
                                 const cuuint32_t*, CUtensorMapInterleave, CUtensorMapSwizzle,
                                 CUtensorMapL2promotion, CUtensorMapFloatOOBfill);
    EncodeFn encode = nullptr;
    cudaGetDriverEntryPoint("cuTensorMapEncodeTiled", (void**)&encode,
                            cudaEnableDefault, nullptr);

    CUtensorMap tmap;
    cuuint64_t dims[5]    = {128, 32, 32, 6, 8};            // d, gx, gy, l, b
    cuuint64_t strides[4] = {768ull * 4,                    // gx: 3072 B
                             32ull * 768 * 4,               // gy: 98304 B
                             128ull * 4,                    // l:  512 B
                             1024ull * 768 * 4};            // b:  3145728 B
    cuuint32_t box[5] = {128, 12, 12, 1, 1};
    cuuint32_t es[5]  = {1, 1, 1, 1, 1};
    encode(&tmap, CU_TENSOR_MAP_DATA_TYPE_FLOAT32, 5, (void*)in,
           dims, strides, box, es,
           CU_TENSOR_MAP_INTERLEAVE_NONE, CU_TENSOR_MAP_SWIZZLE_NONE,
           CU_TENSOR_MAP_L2_PROMOTION_L2_128B, CU_TENSOR_MAP_FLOAT_OOB_FILL_NONE);

    cudaFuncSetAttribute(attn_kernel,
                         cudaFuncAttributeMaxDynamicSharedMemorySize, SMEM_TOTAL);

    norm_kernel<<<ROWS / 32, 256>>>(in);   // 1536 blocks

    cudaLaunchConfig_t cfg = {};
    cfg.gridDim  = dim3(768, 1, 1);        // 48 slices x 16 tiles
    cfg.blockDim = dim3(256, 1, 1);
    cfg.dynamicSmemBytes = SMEM_TOTAL;
    cudaLaunchAttribute attr[1];
    attr[0].id = cudaLaunchAttributeProgrammaticStreamSerialization;
    attr[0].val.programmaticStreamSerializationAllowed = 1;
    cfg.attrs = attr;
    cfg.numAttrs = 1;
    cudaLaunchKernelEx(&cfg, attn_kernel, tmap, out);
}